// round 14
// baseline (speedup 1.0000x reference)
#include <cuda_runtime.h>
#include <cuda_fp16.h>
#include <cstdint>
#include <cstddef>

#define D_DIM   1024
#define NBATCH  16
#define NROWS   (NBATCH * D_DIM)

#define BM 128
#define BN 128
#define BK 64
#define NSTG 3

#define TILE_BYTES  (BM * 128)           // 16 KB
#define STAGE_BYTES (2 * TILE_BYTES)     // 32 KB
#define SMEM_BYTES  (NSTG * STAGE_BYTES) // 96 KB

#define FULL_TILES  888                  // blocks [0,888): whole-K tiles, R12 order
#define TAIL_TILES  136                  // tiles [888,1024): K-split in half
#define TAIL_ITEMS  (2 * TAIL_TILES)     // 272, blocks [888,1160)
#define GRID_CTAS   (FULL_TILES + TAIL_ITEMS)

// fp16 normalized-row scratch + split-K state (allocation-free).
// g_flag zero-init; writer sets, finisher clears -> replay-safe.
__device__ __half g_ra[(size_t)NBATCH * D_DIM * D_DIM];
__device__ __half g_rb[(size_t)NBATCH * D_DIM * D_DIM];
__device__ float  g_part[(size_t)TAIL_TILES * BM * BN];
__device__ int    g_flag[TAIL_TILES];

// ---------------------------------------------------------------- helpers
static __device__ __forceinline__ uint32_t smem_u32(const void* p) {
    uint32_t a;
    asm("{ .reg .u64 t; cvta.to.shared.u64 t, %1; cvt.u32.u64 %0, t; }"
        : "=r"(a) : "l"(p));
    return a;
}
static __device__ __forceinline__ uint32_t sw128(uint32_t o) {
    return o ^ ((o >> 3) & 0x70u);
}
static __device__ __forceinline__ void cp16(uint32_t dst, const void* src) {
    asm volatile("cp.async.cg.shared.global [%0], [%1], 16;"
                 :: "r"(dst), "l"(src) : "memory");
}
static __device__ __forceinline__ void ldmatrix_x4(uint32_t* r, uint32_t addr) {
    asm volatile("ldmatrix.sync.aligned.m8n8.x4.shared.b16 {%0,%1,%2,%3}, [%4];"
                 : "=r"(r[0]), "=r"(r[1]), "=r"(r[2]), "=r"(r[3]) : "r"(addr));
}
static __device__ __forceinline__ void mma16816(float* d, const uint32_t* a,
                                                const uint32_t* b) {
    asm volatile(
        "mma.sync.aligned.m16n8k16.row.col.f32.f16.f16.f32 "
        "{%0,%1,%2,%3}, {%4,%5,%6,%7}, {%8,%9}, {%0,%1,%2,%3};"
        : "+f"(d[0]), "+f"(d[1]), "+f"(d[2]), "+f"(d[3])
        : "r"(a[0]), "r"(a[1]), "r"(a[2]), "r"(a[3]), "r"(b[0]), "r"(b[1]));
}

// ---------------------------------------------------------------- normalize
__global__ void __launch_bounds__(128) norm_kernel(const float* __restrict__ a,
                                                   const float* __restrict__ b,
                                                   const float* __restrict__ w) {
    const int row = blockIdx.x;
    const float* src = (blockIdx.y == 0) ? a : b;
    __half* dst = (blockIdx.y == 0) ? g_ra : g_rb;
    const int t = threadIdx.x;

    const float4* s4 = reinterpret_cast<const float4*>(src + (size_t)row * D_DIM);
    const float4* w4 = reinterpret_cast<const float4*>(w);

    float4 x0 = s4[t];       float4 w0 = w4[t];
    float4 x1 = s4[t + 128]; float4 w1 = w4[t + 128];
    float4 v0, v1;
    v0.x = x0.x * w0.x; v0.y = x0.y * w0.y; v0.z = x0.z * w0.z; v0.w = x0.w * w0.w;
    v1.x = x1.x * w1.x; v1.y = x1.y * w1.y; v1.z = x1.z * w1.z; v1.w = x1.w * w1.w;

    float sum = v0.x * v0.x + v0.y * v0.y + v0.z * v0.z + v0.w * v0.w
              + v1.x * v1.x + v1.y * v1.y + v1.z * v1.z + v1.w * v1.w;
#pragma unroll
    for (int o = 16; o > 0; o >>= 1) sum += __shfl_xor_sync(0xFFFFFFFFu, sum, o);

    __shared__ float red[4];
    if ((t & 31) == 0) red[t >> 5] = sum;
    __syncthreads();
    float tot = red[0] + red[1] + red[2] + red[3];
    float s = rsqrtf(fmaxf(tot, 1e-12f));

    __half2* d2 = reinterpret_cast<__half2*>(dst + (size_t)row * D_DIM);
    d2[2 * t + 0]         = __floats2half2_rn(v0.x * s, v0.y * s);
    d2[2 * t + 1]         = __floats2half2_rn(v0.z * s, v0.w * s);
    d2[2 * (t + 128) + 0] = __floats2half2_rn(v1.x * s, v1.y * s);
    d2[2 * (t + 128) + 1] = __floats2half2_rn(v1.z * s, v1.w * s);
}

// ---------------------------------------------------------------- GEMM core
static __device__ __forceinline__ void load_stage(uint32_t stg,
                                                  const __half* gA, const __half* gB,
                                                  int kof, int tid) {
#pragma unroll
    for (int i = 0; i < 8; i++) {
        int q = i * 128 + tid;
        int row = q >> 3;
        int colb = (q & 7) * 16;
        uint32_t so = sw128((uint32_t)(row * 128 + colb));
        cp16(stg + so,              (const char*)(gA + (size_t)row * D_DIM + kof) + colb);
        cp16(stg + TILE_BYTES + so, (const char*)(gB + (size_t)row * D_DIM + kof) + colb);
    }
    asm volatile("cp.async.commit_group;" ::: "memory");
}

#define LD_FRAGS(buf, sT, kk)                                              \
    do {                                                                   \
        const uint32_t kb_ = (kk) * 32;                                    \
        _Pragma("unroll")                                                  \
        for (int mt_ = 0; mt_ < 4; mt_++)                                  \
            ldmatrix_x4(af[buf][mt_], (sT) + (aOff[mt_] ^ kb_));           \
        _Pragma("unroll")                                                  \
        for (int nq_ = 0; nq_ < 4; nq_++)                                  \
            ldmatrix_x4(bf[buf][nq_], (sT) + (bOff[nq_] ^ kb_));           \
    } while (0)

#define MMA_ALL(buf)                                                       \
    do {                                                                   \
        _Pragma("unroll")                                                  \
        for (int nq_ = 0; nq_ < 4; nq_++)                                  \
            _Pragma("unroll")                                              \
            for (int mt_ = 0; mt_ < 4; mt_++) {                            \
                mma16816(acc[mt_][2 * nq_ + 0], af[buf][mt_],              \
                         &bf[buf][nq_][0]);                                \
                mma16816(acc[mt_][2 * nq_ + 1], af[buf][mt_],              \
                         &bf[buf][nq_][2]);                                \
            }                                                              \
    } while (0)

// Compile-time NITER_T keeps the full-tile path's codegen identical to R12.
template <int NITER_T>
static __device__ __forceinline__ void gemm_core(uint32_t sb,
                                                 const __half* gA,
                                                 const __half* gB,
                                                 int kbase, int tid,
                                                 const uint32_t aOff[4],
                                                 const uint32_t bOff[4],
                                                 float acc[4][8][4]) {
    uint32_t af[2][4][4], bf[2][4][4];

    // prologue: 2 stages in flight; pre-arm buffer 0 with kk=0 of chunk 0
    load_stage(sb + 0 * STAGE_BYTES, gA, gB, kbase + 0 * BK, tid);
    load_stage(sb + 1 * STAGE_BYTES, gA, gB, kbase + 1 * BK, tid);
    asm volatile("cp.async.wait_group 1;" ::: "memory");
    __syncthreads();
    LD_FRAGS(0, sb + 0 * STAGE_BYTES, 0);

#pragma unroll 1
    for (int it = 0; it < NITER_T; it++) {
        const uint32_t sT = sb + (it % NSTG) * STAGE_BYTES;

        // Writes stage (it+2)%3 == (it-1)%3: last read in iteration it-1,
        // strictly before the barrier at the tail of iteration it-1.
        if (it + 2 < NITER_T)
            load_stage(sb + ((it + 2) % NSTG) * STAGE_BYTES, gA, gB,
                       kbase + (it + 2) * BK, tid);
        else
            asm volatile("cp.async.commit_group;" ::: "memory");

        LD_FRAGS(1, sT, 1);
        MMA_ALL(0);
        LD_FRAGS(0, sT, 2);
        MMA_ALL(1);
        LD_FRAGS(1, sT, 3);
        MMA_ALL(0);

        if (it + 1 < NITER_T) {
            // Groups committed: 0..it+2; wait_group 1 => chunk it+1 resident.
            asm volatile("cp.async.wait_group 1;" ::: "memory");
            __syncthreads();
            // Prefetch next iteration's kk=0 under the trailing MMA block.
            LD_FRAGS(0, sb + ((it + 1) % NSTG) * STAGE_BYTES, 0);
        }
        MMA_ALL(1);
    }
}

// Item map: blocks [0,888) = full tiles in R12's exact order (L2 panel
// locality preserved); blocks [888,1160) = K-split halves of tiles
// [888,1024), forming the short FINAL wave (LPT). Writer (even j) precedes
// finisher (odd j) in ID order => writer scheduled no later than finisher.
__global__ void __launch_bounds__(128, 2) gemm_kernel(float* __restrict__ out) {
    extern __shared__ char smem[];
    const uint32_t sb = smem_u32(smem);
    const int tid  = threadIdx.x;
    const int wid  = tid >> 5;
    const int lane = tid & 31;
    const int wm   = wid & 1;        // 2 warps along M: 64 rows each
    const int wn   = wid >> 1;       // 2 warps along N: 64 cols each

    const int item = blockIdx.x;
    int t, kbase, mode, tt = 0;
    if (item < FULL_TILES) {
        t = item; kbase = 0; mode = 0;
    } else {
        int j = item - FULL_TILES;
        tt = j >> 1;
        t = FULL_TILES + tt;
        kbase = (j & 1) * (D_DIM / 2);
        mode = 1 + (j & 1);          // 1 = K-low writer, 2 = K-high finisher
    }
    const int batch = t >> 6;
    const int bm0 = ((t >> 3) & 7) * BM;
    const int bn0 = (t & 7) * BN;

    const __half* gA = g_ra + (size_t)batch * (D_DIM * D_DIM) + (size_t)bm0 * D_DIM;
    const __half* gB = g_rb + (size_t)batch * (D_DIM * D_DIM) + (size_t)bn0 * D_DIM;

    // Swizzled ldmatrix bases; kb = kk*32 occupies bits 5-6 (zero in the
    // unswizzled base), so sw128(base+kb) == sw128(base) ^ kb.
    const int aRow  = lane & 15;
    const int aColb = (lane >> 4) << 4;
    const int bRow  = ((lane >> 4) << 3) + (lane & 7);
    const int bColb = ((lane >> 3) & 1) << 4;

    uint32_t aOff[4], bOff[4];
#pragma unroll
    for (int mt = 0; mt < 4; mt++)
        aOff[mt] = sw128((uint32_t)((wm * 64 + mt * 16 + aRow) * 128 + aColb));
#pragma unroll
    for (int nq = 0; nq < 4; nq++)
        bOff[nq] = sw128((uint32_t)((wn * 64 + nq * 16 + bRow) * 128 + bColb))
                 + TILE_BYTES;

    float acc[4][8][4];
#pragma unroll
    for (int i = 0; i < 4; i++)
#pragma unroll
        for (int j = 0; j < 8; j++)
#pragma unroll
            for (int v = 0; v < 4; v++) acc[i][j][v] = 0.0f;

    if (mode == 0)
        gemm_core<16>(sb, gA, gB, kbase, tid, aOff, bOff, acc);
    else
        gemm_core<8>(sb, gA, gB, kbase, tid, aOff, bOff, acc);

    // ---------------- epilogues
    if (mode == 0) {
        float* oB = out + (size_t)batch * (D_DIM * D_DIM);
#pragma unroll
        for (int mt = 0; mt < 4; mt++) {
            int row = bm0 + wm * 64 + mt * 16 + (lane >> 2);
#pragma unroll
            for (int nt = 0; nt < 8; nt++) {
                int col = bn0 + wn * 64 + nt * 8 + (lane & 3) * 2;
                *reinterpret_cast<float2*>(oB + (size_t)row * D_DIM + col) =
                    make_float2(acc[mt][nt][0], acc[mt][nt][1]);
                *reinterpret_cast<float2*>(oB + (size_t)(row + 8) * D_DIM + col) =
                    make_float2(acc[mt][nt][2], acc[mt][nt][3]);
            }
        }
    } else if (mode == 1) {
        float* pB = g_part + (size_t)tt * (BM * BN);
#pragma unroll
        for (int mt = 0; mt < 4; mt++) {
            int rowl = wm * 64 + mt * 16 + (lane >> 2);
#pragma unroll
            for (int nt = 0; nt < 8; nt++) {
                int coll = wn * 64 + nt * 8 + (lane & 3) * 2;
                *reinterpret_cast<float2*>(pB + rowl * BN + coll) =
                    make_float2(acc[mt][nt][0], acc[mt][nt][1]);
                *reinterpret_cast<float2*>(pB + (rowl + 8) * BN + coll) =
                    make_float2(acc[mt][nt][2], acc[mt][nt][3]);
            }
        }
        __syncthreads();
        if (tid == 0) {
            __threadfence();
            atomicExch(&g_flag[tt], 1);
        }
    } else {
        if (tid == 0) {
            while (atomicAdd(&g_flag[tt], 0) == 0) __nanosleep(64);
            __threadfence();
        }
        __syncthreads();
        const float* pB = g_part + (size_t)tt * (BM * BN);
        float* oB = out + (size_t)batch * (D_DIM * D_DIM);
#pragma unroll
        for (int mt = 0; mt < 4; mt++) {
            int rowl = wm * 64 + mt * 16 + (lane >> 2);
            int row = bm0 + rowl;
#pragma unroll
            for (int nt = 0; nt < 8; nt++) {
                int coll = wn * 64 + nt * 8 + (lane & 3) * 2;
                int col = bn0 + coll;
                float p00 = __ldcg(pB + rowl * BN + coll);
                float p01 = __ldcg(pB + rowl * BN + coll + 1);
                float p10 = __ldcg(pB + (rowl + 8) * BN + coll);
                float p11 = __ldcg(pB + (rowl + 8) * BN + coll + 1);
                *reinterpret_cast<float2*>(oB + (size_t)row * D_DIM + col) =
                    make_float2(acc[mt][nt][0] + p00, acc[mt][nt][1] + p01);
                *reinterpret_cast<float2*>(oB + (size_t)(row + 8) * D_DIM + col) =
                    make_float2(acc[mt][nt][2] + p10, acc[mt][nt][3] + p11);
            }
        }
        __syncthreads();
        if (tid == 0) g_flag[tt] = 0;   // restore initial state for replay
    }
}

// ---------------------------------------------------------------- launch
extern "C" void kernel_launch(void* const* d_in, const int* in_sizes, int n_in,
                              void* d_out, int out_size) {
    const float* a = (const float*)d_in[0];
    const float* b = (const float*)d_in[1];
    const float* w = (const float*)d_in[2];
    float* out = (float*)d_out;

    norm_kernel<<<dim3(NROWS, 2, 1), 128>>>(a, b, w);

    cudaFuncSetAttribute(gemm_kernel, cudaFuncAttributeMaxDynamicSharedMemorySize,
                         SMEM_BYTES);
    gemm_kernel<<<GRID_CTAS, 128, SMEM_BYTES>>>(out);
}

// round 15
// speedup vs baseline: 1.1335x; 1.1335x over previous
#include <cuda_runtime.h>
#include <cuda_fp16.h>
#include <cstdint>
#include <cstddef>

#define D_DIM   1024
#define NBATCH  16
#define NROWS   (NBATCH * D_DIM)

#define BM 128
#define BN 128
#define BK 64                  // fp16 per K-chunk = 128B row (SW128)
#define NSTG 3
#define NITER (D_DIM / BK)     // 16

#define TILE_BYTES  (BM * 128)           // 16 KB
#define STAGE_BYTES (2 * TILE_BYTES)     // 32 KB
#define SMEM_BYTES  (NSTG * STAGE_BYTES) // 96 KB

// fp16 normalized-row scratch (allocation-free: __device__ globals)
__device__ __half g_ra[(size_t)NBATCH * D_DIM * D_DIM];
__device__ __half g_rb[(size_t)NBATCH * D_DIM * D_DIM];

// ---------------------------------------------------------------- helpers
static __device__ __forceinline__ uint32_t smem_u32(const void* p) {
    uint32_t a;
    asm("{ .reg .u64 t; cvta.to.shared.u64 t, %1; cvt.u32.u64 %0, t; }"
        : "=r"(a) : "l"(p));
    return a;
}
static __device__ __forceinline__ uint32_t sw128(uint32_t o) {
    return o ^ ((o >> 3) & 0x70u);
}
static __device__ __forceinline__ void cp16(uint32_t dst, const void* src) {
    asm volatile("cp.async.cg.shared.global [%0], [%1], 16;"
                 :: "r"(dst), "l"(src) : "memory");
}
static __device__ __forceinline__ void ldmatrix_x4(uint32_t* r, uint32_t addr) {
    asm volatile("ldmatrix.sync.aligned.m8n8.x4.shared.b16 {%0,%1,%2,%3}, [%4];"
                 : "=r"(r[0]), "=r"(r[1]), "=r"(r[2]), "=r"(r[3]) : "r"(addr));
}
static __device__ __forceinline__ void mma16816(float* d, const uint32_t* a,
                                                const uint32_t* b) {
    asm volatile(
        "mma.sync.aligned.m16n8k16.row.col.f32.f16.f16.f32 "
        "{%0,%1,%2,%3}, {%4,%5,%6,%7}, {%8,%9}, {%0,%1,%2,%3};"
        : "+f"(d[0]), "+f"(d[1]), "+f"(d[2]), "+f"(d[3])
        : "r"(a[0]), "r"(a[1]), "r"(a[2]), "r"(a[3]), "r"(b[0]), "r"(b[1]));
}
// Streaming store: output is never re-read -> evict-first, protect A/B panels in L2.
static __device__ __forceinline__ void stcs2(float* p, float x, float y) {
    float2 v = make_float2(x, y);
    asm volatile("st.global.cs.v2.f32 [%0], {%1, %2};"
                 :: "l"(p), "f"(v.x), "f"(v.y) : "memory");
}

// ---------------------------------------------------------------- normalize
__global__ void __launch_bounds__(128) norm_kernel(const float* __restrict__ a,
                                                   const float* __restrict__ b,
                                                   const float* __restrict__ w) {
    const int row = blockIdx.x;
    const float* src = (blockIdx.y == 0) ? a : b;
    __half* dst = (blockIdx.y == 0) ? g_ra : g_rb;
    const int t = threadIdx.x;

    const float4* s4 = reinterpret_cast<const float4*>(src + (size_t)row * D_DIM);
    const float4* w4 = reinterpret_cast<const float4*>(w);

    float4 x0 = s4[t];       float4 w0 = w4[t];
    float4 x1 = s4[t + 128]; float4 w1 = w4[t + 128];
    float4 v0, v1;
    v0.x = x0.x * w0.x; v0.y = x0.y * w0.y; v0.z = x0.z * w0.z; v0.w = x0.w * w0.w;
    v1.x = x1.x * w1.x; v1.y = x1.y * w1.y; v1.z = x1.z * w1.z; v1.w = x1.w * w1.w;

    float sum = v0.x * v0.x + v0.y * v0.y + v0.z * v0.z + v0.w * v0.w
              + v1.x * v1.x + v1.y * v1.y + v1.z * v1.z + v1.w * v1.w;
#pragma unroll
    for (int o = 16; o > 0; o >>= 1) sum += __shfl_xor_sync(0xFFFFFFFFu, sum, o);

    __shared__ float red[4];
    if ((t & 31) == 0) red[t >> 5] = sum;
    __syncthreads();
    float tot = red[0] + red[1] + red[2] + red[3];
    float s = rsqrtf(fmaxf(tot, 1e-12f));

    __half2* d2 = reinterpret_cast<__half2*>(dst + (size_t)row * D_DIM);
    d2[2 * t + 0]         = __floats2half2_rn(v0.x * s, v0.y * s);
    d2[2 * t + 1]         = __floats2half2_rn(v0.z * s, v0.w * s);
    d2[2 * (t + 128) + 0] = __floats2half2_rn(v1.x * s, v1.y * s);
    d2[2 * (t + 128) + 1] = __floats2half2_rn(v1.z * s, v1.w * s);
}

// ---------------------------------------------------------------- GEMM
// 128x128 block tile, 4 warps (64x64 each), NSTG=3, reg double-buffered
// fragments, barrier rotated into the last MMA block of each iteration so the
// next iteration's first fragment loads hide under tensor work. (R12 config.)
static __device__ __forceinline__ void load_stage(uint32_t stg,
                                                  const __half* gA, const __half* gB,
                                                  int kof, int tid) {
#pragma unroll
    for (int i = 0; i < 8; i++) {
        int q = i * 128 + tid;      // 1024 16B segments per operand tile
        int row = q >> 3;
        int colb = (q & 7) * 16;
        uint32_t so = sw128((uint32_t)(row * 128 + colb));
        cp16(stg + so,              (const char*)(gA + (size_t)row * D_DIM + kof) + colb);
        cp16(stg + TILE_BYTES + so, (const char*)(gB + (size_t)row * D_DIM + kof) + colb);
    }
    asm volatile("cp.async.commit_group;" ::: "memory");
}

__global__ void __launch_bounds__(128, 2) gemm_kernel(float* __restrict__ out) {
    extern __shared__ char smem[];
    const uint32_t sb = smem_u32(smem);
    const int tid  = threadIdx.x;
    const int wid  = tid >> 5;
    const int lane = tid & 31;
    const int wm   = wid & 1;        // 2 warps along M: 64 rows each
    const int wn   = wid >> 1;       // 2 warps along N: 64 cols each
    const int bn0   = blockIdx.x * BN;
    const int bm0   = blockIdx.y * BM;
    const int batch = blockIdx.z;

    const __half* gA = g_ra + (size_t)batch * (D_DIM * D_DIM) + (size_t)bm0 * D_DIM;
    const __half* gB = g_rb + (size_t)batch * (D_DIM * D_DIM) + (size_t)bn0 * D_DIM;

    float acc[4][8][4];
#pragma unroll
    for (int i = 0; i < 4; i++)
#pragma unroll
        for (int j = 0; j < 8; j++)
#pragma unroll
            for (int v = 0; v < 4; v++) acc[i][j][v] = 0.0f;

    // Swizzled ldmatrix bases; kb = kk*32 occupies bits 5-6 which are zero in
    // the unswizzled base, so sw128(base+kb) == sw128(base) ^ kb.
    const int aRow  = lane & 15;
    const int aColb = (lane >> 4) << 4;
    const int bRow  = ((lane >> 4) << 3) + (lane & 7);
    const int bColb = ((lane >> 3) & 1) << 4;

    uint32_t aOff[4], bOff[4];
#pragma unroll
    for (int mt = 0; mt < 4; mt++)
        aOff[mt] = sw128((uint32_t)((wm * 64 + mt * 16 + aRow) * 128 + aColb));
#pragma unroll
    for (int nq = 0; nq < 4; nq++)
        bOff[nq] = sw128((uint32_t)((wn * 64 + nq * 16 + bRow) * 128 + bColb))
                 + TILE_BYTES;

    // Double-buffered fragments
    uint32_t af[2][4][4], bf[2][4][4];

#define LD_FRAGS(buf, sT, kk)                                              \
    do {                                                                   \
        const uint32_t kb_ = (kk) * 32;                                    \
        _Pragma("unroll")                                                  \
        for (int mt_ = 0; mt_ < 4; mt_++)                                  \
            ldmatrix_x4(af[buf][mt_], (sT) + (aOff[mt_] ^ kb_));           \
        _Pragma("unroll")                                                  \
        for (int nq_ = 0; nq_ < 4; nq_++)                                  \
            ldmatrix_x4(bf[buf][nq_], (sT) + (bOff[nq_] ^ kb_));           \
    } while (0)

#define MMA_ALL(buf)                                                       \
    do {                                                                   \
        _Pragma("unroll")                                                  \
        for (int nq_ = 0; nq_ < 4; nq_++)                                  \
            _Pragma("unroll")                                              \
            for (int mt_ = 0; mt_ < 4; mt_++) {                            \
                mma16816(acc[mt_][2 * nq_ + 0], af[buf][mt_],              \
                         &bf[buf][nq_][0]);                                \
                mma16816(acc[mt_][2 * nq_ + 1], af[buf][mt_],              \
                         &bf[buf][nq_][2]);                                \
            }                                                              \
    } while (0)

    // prologue: 2 stages in flight; pre-arm buffer 0 with chunk0 kk=0
    load_stage(sb + 0 * STAGE_BYTES, gA, gB, 0 * BK, tid);
    load_stage(sb + 1 * STAGE_BYTES, gA, gB, 1 * BK, tid);
    asm volatile("cp.async.wait_group 1;" ::: "memory");   // chunk 0 resident
    __syncthreads();
    LD_FRAGS(0, sb + 0 * STAGE_BYTES, 0);

#pragma unroll 1
    for (int it = 0; it < NITER; it++) {
        const uint32_t sT = sb + (it % NSTG) * STAGE_BYTES;

        // Writes stage (it+2)%3 == (it-1)%3: last read in iteration it-1,
        // strictly before the barrier at the tail of iteration it-1.
        if (it + 2 < NITER)
            load_stage(sb + ((it + 2) % NSTG) * STAGE_BYTES, gA, gB, (it + 2) * BK, tid);
        else
            asm volatile("cp.async.commit_group;" ::: "memory");

        // buffer0 already holds kk=0 fragments (prefetched last iteration)
        LD_FRAGS(1, sT, 1);
        MMA_ALL(0);
        LD_FRAGS(0, sT, 2);
        MMA_ALL(1);
        LD_FRAGS(1, sT, 3);
        MMA_ALL(0);

        if (it + 1 < NITER) {
            // Committed groups now: 0..it+2; wait_group 1 => chunk it+1
            // resident. Barrier: all warps finished reading stage it%3 and
            // (it-1)%3 above, so iteration it+1 may overwrite (it-1)%3.
            asm volatile("cp.async.wait_group 1;" ::: "memory");
            __syncthreads();
            // Prefetch next iteration's kk=0 under the trailing MMA block.
            LD_FRAGS(0, sb + ((it + 1) % NSTG) * STAGE_BYTES, 0);
        }
        MMA_ALL(1);
    }

    // epilogue: c0,c1 -> (m = lane>>2, n = (lane&3)*2); c2,c3 -> m+8.
    // Streaming (.cs) stores: output is write-once, keep panels in L2.
    float* oB = out + (size_t)batch * (D_DIM * D_DIM);
#pragma unroll
    for (int mt = 0; mt < 4; mt++) {
        int row = bm0 + wm * 64 + mt * 16 + (lane >> 2);
#pragma unroll
        for (int nt = 0; nt < 8; nt++) {
            int col = bn0 + wn * 64 + nt * 8 + (lane & 3) * 2;
            stcs2(oB + (size_t)row * D_DIM + col,
                  acc[mt][nt][0], acc[mt][nt][1]);
            stcs2(oB + (size_t)(row + 8) * D_DIM + col,
                  acc[mt][nt][2], acc[mt][nt][3]);
        }
    }
}

// ---------------------------------------------------------------- launch
extern "C" void kernel_launch(void* const* d_in, const int* in_sizes, int n_in,
                              void* d_out, int out_size) {
    const float* a = (const float*)d_in[0];
    const float* b = (const float*)d_in[1];
    const float* w = (const float*)d_in[2];
    float* out = (float*)d_out;

    norm_kernel<<<dim3(NROWS, 2, 1), 128>>>(a, b, w);

    cudaFuncSetAttribute(gemm_kernel, cudaFuncAttributeMaxDynamicSharedMemorySize,
                         SMEM_BYTES);
    gemm_kernel<<<dim3(D_DIM / BN, D_DIM / BM, NBATCH), 128, SMEM_BYTES>>>(out);
}